// round 4
// baseline (speedup 1.0000x reference)
#include <cuda_runtime.h>
#include <cuda_bf16.h>
#include <cstdint>
#include <math.h>

// ---------------------------------------------------------------------------
// TelephoneAttentionND  (B=2, L=2048, C=1024, H=16, D=64, K=64, S=33)
// cvt   : x, w_kern, w_out -> tf32 bit buffers
// Stage 1: tiled wave(32)+exp(1) projection + activations -> freq/phase/expo
// Stage 2: kern GEMM [tf32 mma.sync, cp.async 4-stage] (+bias) -> g_proj
// Stage 3: rmsnorm(1024)+silu                                  -> g_kmax
// Stage 4: attention gather/einsum (2-phase), writes tf32      -> g_ha
// Stage 5: out GEMM [tf32 mma.sync, cp.async 4-stage] + silu   -> d_out
// ---------------------------------------------------------------------------

#define BATCH 2
#define SEQLEN 2048
#define CH 1024
#define NHEAD 16
#define HDIM 64
#define KSIZE 64
#define TOKENS (BATCH * SEQLEN)   // 4096

// scratch (device globals; no allocation allowed)
__device__ float g_freq[TOKENS * NHEAD];
__device__ float g_phase[TOKENS * NHEAD];
__device__ float g_expo[TOKENS];
__device__ float g_proj[(size_t)TOKENS * CH];     // gemm1 out (fp32)
__device__ float g_kmax[(size_t)TOKENS * CH];     // rmsnorm+silu out
__device__ uint32_t g_xa[(size_t)TOKENS * CH];    // x in tf32 bits
__device__ uint32_t g_ha[(size_t)TOKENS * CH];    // hidden in tf32 bits
__device__ uint32_t g_wk[(size_t)CH * CH];        // w_kern tf32 bits
__device__ uint32_t g_wo[(size_t)CH * CH];        // w_out tf32 bits

__device__ __forceinline__ float siluf(float v) {
    return v / (1.0f + expf(-v));
}

__device__ __forceinline__ uint32_t f2tf32(float x) {
    uint32_t r;
    asm("cvt.rna.tf32.f32 %0, %1;" : "=r"(r) : "f"(x));
    return r;
}

__device__ __forceinline__ void mma_tf32_16x8x8(
    float c[4], const uint32_t a[4], const uint32_t b[2])
{
    asm volatile(
        "mma.sync.aligned.m16n8k8.row.col.f32.tf32.tf32.f32 "
        "{%0, %1, %2, %3}, {%4, %5, %6, %7}, {%8, %9}, {%0, %1, %2, %3};"
        : "+f"(c[0]), "+f"(c[1]), "+f"(c[2]), "+f"(c[3])
        : "r"(a[0]), "r"(a[1]), "r"(a[2]), "r"(a[3]), "r"(b[0]), "r"(b[1]));
}

__device__ __forceinline__ uint32_t smem_u32(const void* p) {
    uint32_t a;
    asm("{ .reg .u64 t; cvta.to.shared.u64 t, %1; cvt.u32.u64 %0, t; }"
        : "=r"(a) : "l"(p));
    return a;
}

__device__ __forceinline__ void cp_async16(uint32_t dst, const void* src) {
    asm volatile("cp.async.ca.shared.global [%0], [%1], 16;"
                 :: "r"(dst), "l"(src));
}
#define CP_COMMIT() asm volatile("cp.async.commit_group;" ::: "memory")
#define CP_WAIT2()  asm volatile("cp.async.wait_group 2;" ::: "memory")

// ===========================================================================
// cvt: fp32 -> tf32 bits (rna), vectorized
// ===========================================================================
__global__ __launch_bounds__(256) void cvt_tf32_kernel(
    const float* __restrict__ in, uint32_t* __restrict__ out, int n4)
{
    const int idx = blockIdx.x * 256 + threadIdx.x;
    if (idx < n4) {
        const float4 v = ((const float4*)in)[idx];
        uint4 o;
        o.x = f2tf32(v.x); o.y = f2tf32(v.y);
        o.z = f2tf32(v.z); o.w = f2tf32(v.w);
        ((uint4*)out)[idx] = o;
    }
}

// ===========================================================================
// Stage 1: tiled wave+exp projection. 128 blocks x 32 tokens, 256 threads.
// ===========================================================================
__global__ __launch_bounds__(256) void proj_small_kernel(
    const float* __restrict__ x,
    const float* __restrict__ w_wave, const float* __restrict__ b_wave,
    const float* __restrict__ g_wave,
    const float* __restrict__ w_exp, const float* __restrict__ b_exp,
    const float* __restrict__ g_exp)
{
    const int t0 = blockIdx.x * 32;
    __shared__ float xs[32][33];   // [k][token]
    __shared__ float ws[32][34];   // [k][o] (33 outputs)
    __shared__ float po[32][34];   // [token][o]

    const int tid = threadIdx.x;
    const int tt  = tid & 31;      // token within block
    const int og  = tid >> 5;      // output group 0..7
    const int obase = og * 4;
    const bool five = (og == 7);   // group 7 also handles o=32 (exp)

    float acc[5] = {0.f, 0.f, 0.f, 0.f, 0.f};

    for (int k0 = 0; k0 < CH; k0 += 32) {
        {
            const int token = tid >> 3, c4 = tid & 7;
            const float4 v = *(const float4*)(x + (size_t)(t0 + token) * CH + k0 + c4 * 4);
            xs[c4 * 4 + 0][token] = v.x; xs[c4 * 4 + 1][token] = v.y;
            xs[c4 * 4 + 2][token] = v.z; xs[c4 * 4 + 3][token] = v.w;
        }
        for (int fi = tid; fi < 33 * 8; fi += 256) {
            const int o = fi >> 3, c4 = fi & 7;
            const float* wr = (o < 32) ? (w_wave + (size_t)o * CH) : w_exp;
            const float4 v = *(const float4*)(wr + k0 + c4 * 4);
            ws[c4 * 4 + 0][o] = v.x; ws[c4 * 4 + 1][o] = v.y;
            ws[c4 * 4 + 2][o] = v.z; ws[c4 * 4 + 3][o] = v.w;
        }
        __syncthreads();
        #pragma unroll
        for (int k = 0; k < 32; k++) {
            const float xv = xs[k][tt];
            acc[0] += xv * ws[k][obase + 0];
            acc[1] += xv * ws[k][obase + 1];
            acc[2] += xv * ws[k][obase + 2];
            acc[3] += xv * ws[k][obase + 3];
            if (five) acc[4] += xv * ws[k][32];
        }
        __syncthreads();
    }

    po[tt][obase + 0] = acc[0] + b_wave[obase + 0];
    po[tt][obase + 1] = acc[1] + b_wave[obase + 1];
    po[tt][obase + 2] = acc[2] + b_wave[obase + 2];
    po[tt][obase + 3] = acc[3] + b_wave[obase + 3];
    if (five) po[tt][32] = acc[4] + b_exp[0];
    __syncthreads();

    // activations: 8 warps x 4 rounds cover 32 tokens
    const int wid = tid >> 5, lane = tid & 31;
    for (int it = 0; it < 4; it++) {
        const int tk = wid * 4 + it;
        const int gtok = t0 + tk;
        float v = po[tk][lane];
        float sq = v * v;
        #pragma unroll
        for (int d = 16; d > 0; d >>= 1) sq += __shfl_xor_sync(0xffffffffu, sq, d);
        const float r = rsqrtf(sq * (1.0f / 32.0f) + 1e-6f);
        const float sil = siluf(g_wave[lane] * v * r);
        if (lane < 16) {
            g_freq[(size_t)gtok * NHEAD + lane] = 15.0f / (1.0f + expf(-sil)) + 1.0f;
        } else {
            g_phase[(size_t)gtok * NHEAD + (lane - 16)] = tanhf(sil) * 16.0f;
        }
        if (lane == 0) {
            const float ve = po[tk][32];
            const float y = g_exp[0] * ve * rsqrtf(ve * ve + 1e-6f);
            g_expo[gtok] = (1.0f / (1.0f + expf(-y))) * 3.5f + 0.5f;
        }
    }
}

// ===========================================================================
// Stages 2 & 5: tf32 mma.sync GEMM with cp.async 4-stage pipeline.
// C[M,N] = A[M,K]*B[N,K]^T. Operands pre-converted to tf32 bits.
// 128x128 CTA tile, 8 warps (2x4), warp = 64x32 via 4x4 m16n8k8.
// smem row stride 20 -> conflict-free fragment LDS. Dynamic smem 80KB.
// ===========================================================================
#define GSTRIDE 20
#define STG 4
#define STAGE_U32 (128 * GSTRIDE)                       // 2560 u32 per matrix stage
#define GEMM_SMEM (STG * STAGE_U32 * 2 * 4)             // 81920 bytes

template <bool BIAS, bool SILU>
__global__ __launch_bounds__(256) void gemm_tc_kernel(
    const uint32_t* __restrict__ A, const uint32_t* __restrict__ B,
    const float* __restrict__ bias, float* __restrict__ C)
{
    extern __shared__ uint32_t smem32[];
    const uint32_t smem_base = smem_u32(smem32);

    const int tid  = threadIdx.x;
    const int wid  = tid >> 5;
    const int lane = tid & 31;
    const int gid  = lane >> 2;     // groupID 0..7
    const int tig  = lane & 3;      // thread-in-group 0..3
    const int wm   = wid & 1;       // warp row (0..1) -> 64 rows each
    const int wn   = wid >> 1;      // warp col (0..3) -> 32 cols each

    const int bm = blockIdx.y * 128;
    const int bn = blockIdx.x * 128;
    const uint32_t* gA = A + (size_t)bm * CH;
    const uint32_t* gB = B + (size_t)bn * CH;

    // cp.async mapping: 512 float4 per matrix per stage; 2 per thread.
    const int r0 = (tid + 0)   >> 2, c0 = ((tid + 0)   & 3) * 4;
    const int r1 = (tid + 256) >> 2, c1 = ((tid + 256) & 3) * 4;
    const uint32_t a_s0 = smem_base + (uint32_t)(r0 * GSTRIDE + c0) * 4;
    const uint32_t a_s1 = smem_base + (uint32_t)(r1 * GSTRIDE + c1) * 4;
    const uint32_t b_s0 = a_s0 + STG * STAGE_U32 * 4;
    const uint32_t b_s1 = a_s1 + STG * STAGE_U32 * 4;
    const uint32_t* gA0 = gA + (size_t)r0 * CH + c0;
    const uint32_t* gA1 = gA + (size_t)r1 * CH + c1;
    const uint32_t* gB0 = gB + (size_t)r0 * CH + c0;
    const uint32_t* gB1 = gB + (size_t)r1 * CH + c1;

    float c[4][4][4];
    #pragma unroll
    for (int mt = 0; mt < 4; mt++)
        #pragma unroll
        for (int nt = 0; nt < 4; nt++)
            #pragma unroll
            for (int j = 0; j < 4; j++) c[mt][nt][j] = 0.0f;

    const int NCHUNK = CH / 16;   // 64

    // prologue: stages 0..2
    #pragma unroll
    for (int s = 0; s < STG - 1; s++) {
        const uint32_t so = (uint32_t)(s * STAGE_U32) * 4;
        const int k0 = s * 16;
        cp_async16(a_s0 + so, gA0 + k0);
        cp_async16(a_s1 + so, gA1 + k0);
        cp_async16(b_s0 + so, gB0 + k0);
        cp_async16(b_s1 + so, gB1 + k0);
        CP_COMMIT();
    }

    for (int kc = 0; kc < NCHUNK; kc++) {
        CP_WAIT2();
        __syncthreads();

        // issue stage kc+3 (overwrites buffer consumed at iter kc-1)
        if (kc + STG - 1 < NCHUNK) {
            const uint32_t so = (uint32_t)(((kc + STG - 1) & (STG - 1)) * STAGE_U32) * 4;
            const int k0 = (kc + STG - 1) * 16;
            cp_async16(a_s0 + so, gA0 + k0);
            cp_async16(a_s1 + so, gA1 + k0);
            cp_async16(b_s0 + so, gB0 + k0);
            cp_async16(b_s1 + so, gB1 + k0);
        }
        CP_COMMIT();

        const uint32_t* Ab = smem32 + (kc & (STG - 1)) * STAGE_U32;
        const uint32_t* Bb = Ab + STG * STAGE_U32;

        #pragma unroll
        for (int ks = 0; ks < 2; ks++) {
            const int kb = ks * 8 + tig;
            uint32_t a[4][4], b[4][2];
            #pragma unroll
            for (int mt = 0; mt < 4; mt++) {
                const int row = wm * 64 + mt * 16 + gid;
                a[mt][0] = Ab[row * GSTRIDE + kb];
                a[mt][1] = Ab[(row + 8) * GSTRIDE + kb];
                a[mt][2] = Ab[row * GSTRIDE + kb + 4];
                a[mt][3] = Ab[(row + 8) * GSTRIDE + kb + 4];
            }
            #pragma unroll
            for (int nt = 0; nt < 4; nt++) {
                const int n = wn * 32 + nt * 8 + gid;
                b[nt][0] = Bb[n * GSTRIDE + kb];
                b[nt][1] = Bb[n * GSTRIDE + kb + 4];
            }
            #pragma unroll
            for (int mt = 0; mt < 4; mt++)
                #pragma unroll
                for (int nt = 0; nt < 4; nt++)
                    mma_tf32_16x8x8(c[mt][nt], a[mt], b[nt]);
        }
    }

    // epilogue
    #pragma unroll
    for (int mt = 0; mt < 4; mt++) {
        const int row = bm + wm * 64 + mt * 16 + gid;
        #pragma unroll
        for (int nt = 0; nt < 4; nt++) {
            const int col = bn + wn * 32 + nt * 8 + tig * 2;
            float u0 = c[mt][nt][0], u1 = c[mt][nt][1];
            float u2 = c[mt][nt][2], u3 = c[mt][nt][3];
            if (BIAS) {
                const float b0v = bias[col], b1v = bias[col + 1];
                u0 += b0v; u1 += b1v; u2 += b0v; u3 += b1v;
            }
            if (SILU) {
                u0 = siluf(u0); u1 = siluf(u1); u2 = siluf(u2); u3 = siluf(u3);
            }
            *(float2*)(C + (size_t)row * CH + col)       = make_float2(u0, u1);
            *(float2*)(C + (size_t)(row + 8) * CH + col) = make_float2(u2, u3);
        }
    }
}

// ===========================================================================
// Stage 3: rmsnorm over 1024 + g_kern scale + silu.
// ===========================================================================
__global__ __launch_bounds__(256) void rmsnorm_silu_kernel(
    const float* __restrict__ gk)
{
    const int token = blockIdx.x;
    const float* p = g_proj + (size_t)token * CH;
    float* o = g_kmax + (size_t)token * CH;

    __shared__ float red[8];
    __shared__ float rbc;
    const int tid  = threadIdx.x;
    const int wid  = tid >> 5;
    const int lane = tid & 31;

    float sq = 0.0f;
    #pragma unroll
    for (int i = tid; i < CH; i += 256) { const float v = p[i]; sq += v * v; }
    #pragma unroll
    for (int d = 16; d > 0; d >>= 1) sq += __shfl_xor_sync(0xffffffffu, sq, d);
    if (lane == 0) red[wid] = sq;
    __syncthreads();
    if (tid == 0) {
        float s = 0.0f;
        #pragma unroll
        for (int i = 0; i < 8; i++) s += red[i];
        rbc = rsqrtf(s * (1.0f / (float)CH) + 1e-6f);
    }
    __syncthreads();
    const float r = rbc;
    #pragma unroll
    for (int i = tid; i < CH; i += 256) {
        o[i] = siluf(gk[i] * p[i] * r);
    }
}

// ===========================================================================
// Stage 4: telephone attention. 1 block/token, 16 warps (1/head).
// Phase A computes fused weights kf = kern*(1-frac), kc = kern*frac.
// Phase B: acc += kf*vf + kc*vc. Output written as tf32 bits (GEMM2 input).
// ===========================================================================
__global__ __launch_bounds__(512) void attn_kernel(const float* __restrict__ x)
{
    const int token = blockIdx.x;
    const int b = token >> 11;
    const int l = token & (SEQLEN - 1);
    const int h    = threadIdx.x >> 5;
    const int lane = threadIdx.x & 31;

    __shared__ float km[NHEAD][KSIZE];
    __shared__ float skf[NHEAD][33];
    __shared__ float skc[NHEAD][33];
    __shared__ int   sfl[NHEAD][33];

    const float* kr = g_kmax + (size_t)token * CH;
    km[h][lane]      = kr[h * KSIZE + lane];
    km[h][lane + 32] = kr[h * KSIZE + lane + 32];

    const float f = g_freq[(size_t)token * NHEAD + h];
    const float p = g_phase[(size_t)token * NHEAD + h];
    const float e = g_expo[token];
    __syncwarp();

    // Phase A: per-sample scalars (lane-parallel)
    for (int s = lane; s < 33; s += 32) {
        const float off = (float)(s - 16);
        const float rel = off * f;
        const float pos = (float)l + rel + p;
        const float validf = (pos >= 0.0f && pos < (float)SEQLEN) ? 1.0f : 0.0f;
        const float pc = fminf(fmaxf(pos, 0.0f), (float)SEQLEN - 1.001f);
        const int   fl = (int)floorf(pc);
        const float frac = pc - (float)fl;
        const float ar = fabsf(rel);
        const float powr = expf(-e * log1pf(ar * (1.0f / (float)SEQLEN)));
        const float idxf = fminf(ar * (1.0f / 256.0f), 1.0f) * 63.0f;
        int i0 = (int)idxf; if (i0 > 62) i0 = 62;
        const float wc = idxf - (float)i0;
        const float kern =
            (km[h][i0] * (1.0f - wc) + km[h][i0 + 1] * wc) * powr * validf;
        skf[h][s] = kern * (1.0f - frac);
        skc[h][s] = kern * frac;
        sfl[h][s] = fl * (CH / 2);
    }
    __syncwarp();

    // Phase B: gather + accumulate. lane covers d=2*lane..2*lane+1.
    const float2* xb = (const float2*)(x + ((size_t)b * SEQLEN) * CH + h * HDIM);
    float acc0 = 0.0f, acc1 = 0.0f;
    #pragma unroll 3
    for (int s = 0; s < 33; s++) {
        const float kf = skf[h][s];
        const float kc = skc[h][s];
        const float2* vfp = xb + sfl[h][s];
        const float2 vf = vfp[lane];
        const float2 vc = vfp[CH / 2 + lane];
        acc0 += kf * vf.x + kc * vc.x;
        acc1 += kf * vf.y + kc * vc.y;
    }

    uint32_t* hp = g_ha + (size_t)token * CH + h * HDIM + lane * 2;
    hp[0] = f2tf32(acc0);
    hp[1] = f2tf32(acc1);
}

// ===========================================================================
// launch
// ===========================================================================
extern "C" void kernel_launch(void* const* d_in, const int* in_sizes, int n_in,
                              void* d_out, int out_size)
{
    const float* x      = (const float*)d_in[0];
    const float* w_wave = (const float*)d_in[1];
    const float* b_wave = (const float*)d_in[2];
    const float* g_wave = (const float*)d_in[3];
    const float* w_kern = (const float*)d_in[4];
    const float* b_kern = (const float*)d_in[5];
    const float* g_kern = (const float*)d_in[6];
    const float* w_exp  = (const float*)d_in[7];
    const float* b_exp  = (const float*)d_in[8];
    const float* g_exp  = (const float*)d_in[9];
    const float* w_out  = (const float*)d_in[10];
    float* out = (float*)d_out;

    float *proj_ptr;
    uint32_t *xa_ptr, *ha_ptr, *wk_ptr, *wo_ptr;
    cudaGetSymbolAddress((void**)&proj_ptr, g_proj);
    cudaGetSymbolAddress((void**)&xa_ptr, g_xa);
    cudaGetSymbolAddress((void**)&ha_ptr, g_ha);
    cudaGetSymbolAddress((void**)&wk_ptr, g_wk);
    cudaGetSymbolAddress((void**)&wo_ptr, g_wo);

    cudaFuncSetAttribute(gemm_tc_kernel<true, false>,
                         cudaFuncAttributeMaxDynamicSharedMemorySize, GEMM_SMEM);
    cudaFuncSetAttribute(gemm_tc_kernel<false, true>,
                         cudaFuncAttributeMaxDynamicSharedMemorySize, GEMM_SMEM);

    // convert GEMM operands to tf32 bits
    cvt_tf32_kernel<<<(TOKENS * CH / 4 + 255) / 256, 256>>>(x, xa_ptr,
                                                            TOKENS * CH / 4);
    cvt_tf32_kernel<<<(CH * CH / 4 + 255) / 256, 256>>>(w_kern, wk_ptr,
                                                        CH * CH / 4);
    cvt_tf32_kernel<<<(CH * CH / 4 + 255) / 256, 256>>>(w_out, wo_ptr,
                                                        CH * CH / 4);

    // Stage 1: wave + exp projections (tiled)
    proj_small_kernel<<<TOKENS / 32, 256>>>(x, w_wave, b_wave, g_wave,
                                            w_exp, b_exp, g_exp);

    // Stage 2: kern projection GEMM (+bias) via tf32 mma.sync
    dim3 ggrid(CH / 128, TOKENS / 128);   // (8, 32)
    gemm_tc_kernel<true, false><<<ggrid, 256, GEMM_SMEM>>>(xa_ptr, wk_ptr,
                                                           b_kern, proj_ptr);

    // Stage 3: rmsnorm + silu -> kernel_max
    rmsnorm_silu_kernel<<<TOKENS, 256>>>(g_kern);

    // Stage 4: gather / interpolate / einsum -> hidden (tf32 bits)
    attn_kernel<<<TOKENS, 512>>>(x);

    // Stage 5: output GEMM + silu via tf32 mma.sync
    gemm_tc_kernel<false, true><<<ggrid, 256, GEMM_SMEM>>>(ha_ptr, wo_ptr,
                                                           nullptr, out);
}

// round 5
// speedup vs baseline: 1.3052x; 1.3052x over previous
#include <cuda_runtime.h>
#include <cuda_bf16.h>
#include <cuda_fp16.h>
#include <cstdint>
#include <math.h>

// ---------------------------------------------------------------------------
// TelephoneAttentionND  (B=2, L=2048, C=1024, H=16, D=64, K=64, S=33)
// cvt   : x, w_kern, w_out -> fp16 buffers
// Stage 1: wave(32)+exp(1) projection + activations (fp32)  -> freq/phase/expo
// Stage 2: kern GEMM [fp16 mma m16n8k16, cp.async] (+bias)  -> g_proj
// Stage 3: rmsnorm(1024)+silu                               -> g_kmax
// Stage 4: attention gather/einsum (2-phase), writes fp16   -> g_ha
// Stage 5: out GEMM [fp16 mma m16n8k16] + silu              -> d_out
// ---------------------------------------------------------------------------

#define BATCH 2
#define SEQLEN 2048
#define CH 1024
#define NHEAD 16
#define HDIM 64
#define KSIZE 64
#define TOKENS (BATCH * SEQLEN)   // 4096

// scratch (device globals; no allocation allowed)
__device__ float g_freq[TOKENS * NHEAD];
__device__ float g_phase[TOKENS * NHEAD];
__device__ float g_expo[TOKENS];
__device__ float g_proj[(size_t)TOKENS * CH];   // gemm1 out (fp32)
__device__ float g_kmax[(size_t)TOKENS * CH];   // rmsnorm+silu out
__device__ __half g_xa[(size_t)TOKENS * CH];    // x in fp16
__device__ __half g_ha[(size_t)TOKENS * CH];    // hidden in fp16
__device__ __half g_wk[(size_t)CH * CH];        // w_kern fp16
__device__ __half g_wo[(size_t)CH * CH];        // w_out fp16

__device__ __forceinline__ float siluf(float v) {
    return v / (1.0f + expf(-v));
}

__device__ __forceinline__ void mma_f16_16x8x16(
    float c[4], const uint32_t a[4], const uint32_t b[2])
{
    asm volatile(
        "mma.sync.aligned.m16n8k16.row.col.f32.f16.f16.f32 "
        "{%0, %1, %2, %3}, {%4, %5, %6, %7}, {%8, %9}, {%0, %1, %2, %3};"
        : "+f"(c[0]), "+f"(c[1]), "+f"(c[2]), "+f"(c[3])
        : "r"(a[0]), "r"(a[1]), "r"(a[2]), "r"(a[3]), "r"(b[0]), "r"(b[1]));
}

__device__ __forceinline__ uint32_t smem_u32(const void* p) {
    uint32_t a;
    asm("{ .reg .u64 t; cvta.to.shared.u64 t, %1; cvt.u32.u64 %0, t; }"
        : "=r"(a) : "l"(p));
    return a;
}

__device__ __forceinline__ void cp_async16(uint32_t dst, const void* src) {
    asm volatile("cp.async.ca.shared.global [%0], [%1], 16;"
                 :: "r"(dst), "l"(src));
}
#define CP_COMMIT() asm volatile("cp.async.commit_group;" ::: "memory")
#define CP_WAIT2()  asm volatile("cp.async.wait_group 2;" ::: "memory")

// ===========================================================================
// cvt: fp32 -> fp16 (rn), vectorized (4 elems/thread)
// ===========================================================================
__global__ __launch_bounds__(256) void cvt_f16_kernel(
    const float* __restrict__ in, __half* __restrict__ out, int n4)
{
    const int idx = blockIdx.x * 256 + threadIdx.x;
    if (idx < n4) {
        const float4 v = ((const float4*)in)[idx];
        __half2 h0 = __floats2half2_rn(v.x, v.y);
        __half2 h1 = __floats2half2_rn(v.z, v.w);
        uint2 o;
        o.x = *(uint32_t*)&h0;
        o.y = *(uint32_t*)&h1;
        ((uint2*)out)[idx] = o;
    }
}

// ===========================================================================
// Stage 1: wave+exp projection (fp32). 256 blocks x 16 tokens, 256 threads.
// Thread (o = lane, tg = warp) accumulates output o for tokens tg and tg+8.
// Lane 0 additionally handles the exp output (o=32).
// ===========================================================================
__global__ __launch_bounds__(256) void proj_small_kernel(
    const float* __restrict__ x,
    const float* __restrict__ w_wave, const float* __restrict__ b_wave,
    const float* __restrict__ g_wave,
    const float* __restrict__ w_exp, const float* __restrict__ b_exp,
    const float* __restrict__ g_exp)
{
    const int t0 = blockIdx.x * 16;
    __shared__ float xs[16][33];   // [token][k]
    __shared__ float ws[32][34];   // [k][o]
    __shared__ float po[16][34];   // [token][o]

    const int tid = threadIdx.x;
    const int tg   = tid >> 5;     // warp / token-group 0..7
    const int o    = tid & 31;     // output (lane)

    float acc0 = 0.f, acc1 = 0.f, ae0 = 0.f, ae1 = 0.f;

    const int ltok = tid >> 4;            // 0..15 (xs load mapping)
    const int lkk  = (tid & 15) * 2;      // 0,2,..,30

    for (int k0 = 0; k0 < CH; k0 += 32) {
        {
            const float2 v = *(const float2*)(x + (size_t)(t0 + ltok) * CH + k0 + lkk);
            xs[ltok][lkk] = v.x; xs[ltok][lkk + 1] = v.y;
        }
        for (int fi = tid; fi < 33 * 8; fi += 256) {
            const int oo = fi >> 3, c4 = fi & 7;
            const float* wr = (oo < 32) ? (w_wave + (size_t)oo * CH) : w_exp;
            const float4 v = *(const float4*)(wr + k0 + c4 * 4);
            ws[c4 * 4 + 0][oo] = v.x; ws[c4 * 4 + 1][oo] = v.y;
            ws[c4 * 4 + 2][oo] = v.z; ws[c4 * 4 + 3][oo] = v.w;
        }
        __syncthreads();
        #pragma unroll
        for (int k = 0; k < 32; k++) {
            const float wv = ws[k][o];
            const float x0 = xs[tg][k];
            const float x1 = xs[tg + 8][k];
            acc0 += x0 * wv;
            acc1 += x1 * wv;
            if (o == 0) {
                const float we = ws[k][32];
                ae0 += x0 * we;
                ae1 += x1 * we;
            }
        }
        __syncthreads();
    }

    const float bw = b_wave[o];
    po[tg][o]     = acc0 + bw;
    po[tg + 8][o] = acc1 + bw;
    if (o == 0) {
        const float be = b_exp[0];
        po[tg][32]     = ae0 + be;
        po[tg + 8][32] = ae1 + be;
    }
    __syncthreads();

    // activations: warp tg handles tokens tg and tg+8
    const int lane = o;
    #pragma unroll
    for (int it = 0; it < 2; it++) {
        const int tk = tg + it * 8;
        const int gtok = t0 + tk;
        float v = po[tk][lane];
        float sq = v * v;
        #pragma unroll
        for (int d = 16; d > 0; d >>= 1) sq += __shfl_xor_sync(0xffffffffu, sq, d);
        const float r = rsqrtf(sq * (1.0f / 32.0f) + 1e-6f);
        const float sil = siluf(g_wave[lane] * v * r);
        if (lane < 16) {
            g_freq[(size_t)gtok * NHEAD + lane] = 15.0f / (1.0f + expf(-sil)) + 1.0f;
        } else {
            g_phase[(size_t)gtok * NHEAD + (lane - 16)] = tanhf(sil) * 16.0f;
        }
        if (lane == 0) {
            const float ve = po[tk][32];
            const float y = g_exp[0] * ve * rsqrtf(ve * ve + 1e-6f);
            g_expo[gtok] = (1.0f / (1.0f + expf(-y))) * 3.5f + 0.5f;
        }
    }
}

// ===========================================================================
// Stages 2 & 5: fp16 mma.sync m16n8k16 GEMM with cp.async 4-stage pipeline.
// C[M,N] = A[M,K]*B[N,K]^T, fp32 accumulate. Operands pre-converted fp16.
// 128x128 CTA tile, 8 warps (2x4), warp = 64x32 via 4x4 m16n8k16.
// smem: half2 words, row stride 12 u32 (8 used + pad) -> conflict-free LDS.
// ===========================================================================
#define GSTRIDE 12                                     // u32 per row
#define STG 4
#define STAGE_U32 (128 * GSTRIDE)                      // 1536 u32 per matrix stage
#define GEMM_SMEM (STG * STAGE_U32 * 2 * 4)            // 49152 bytes

template <bool BIAS, bool SILU>
__global__ __launch_bounds__(256) void gemm_tc_kernel(
    const __half* __restrict__ A, const __half* __restrict__ B,
    const float* __restrict__ bias, float* __restrict__ C)
{
    extern __shared__ uint32_t smem32[];
    const uint32_t smem_base = smem_u32(smem32);

    const int tid  = threadIdx.x;
    const int wid  = tid >> 5;
    const int lane = tid & 31;
    const int gid  = lane >> 2;     // groupID 0..7
    const int tig  = lane & 3;      // thread-in-group 0..3
    const int wm   = wid & 1;       // warp row (0..1) -> 64 rows each
    const int wn   = wid >> 1;      // warp col (0..3) -> 32 cols each

    const int bm = blockIdx.y * 128;
    const int bn = blockIdx.x * 128;

    // cp.async mapping: 128 rows x 16 halves per matrix stage; 256 x 16B.
    const int r0  = tid >> 1;            // 0..127
    const int hr0 = (tid & 1) * 8;       // half offset within row (0 or 8)
    const uint32_t a_s = smem_base + (uint32_t)(r0 * GSTRIDE + (hr0 >> 1)) * 4;
    const uint32_t b_s = a_s + STG * STAGE_U32 * 4;
    const __half* gA0 = A + (size_t)(bm + r0) * CH + hr0;
    const __half* gB0 = B + (size_t)(bn + r0) * CH + hr0;

    float c[4][4][4];
    #pragma unroll
    for (int mt = 0; mt < 4; mt++)
        #pragma unroll
        for (int nt = 0; nt < 4; nt++)
            #pragma unroll
            for (int j = 0; j < 4; j++) c[mt][nt][j] = 0.0f;

    const int NCHUNK = CH / 16;   // 64

    // prologue: stages 0..2
    #pragma unroll
    for (int s = 0; s < STG - 1; s++) {
        const uint32_t so = (uint32_t)(s * STAGE_U32) * 4;
        cp_async16(a_s + so, gA0 + s * 16);
        cp_async16(b_s + so, gB0 + s * 16);
        CP_COMMIT();
    }

    for (int kc = 0; kc < NCHUNK; kc++) {
        CP_WAIT2();
        __syncthreads();

        if (kc + STG - 1 < NCHUNK) {
            const uint32_t so = (uint32_t)(((kc + STG - 1) & (STG - 1)) * STAGE_U32) * 4;
            cp_async16(a_s + so, gA0 + (kc + STG - 1) * 16);
            cp_async16(b_s + so, gB0 + (kc + STG - 1) * 16);
        }
        CP_COMMIT();

        const uint32_t* Ab = smem32 + (kc & (STG - 1)) * STAGE_U32;
        const uint32_t* Bb = Ab + STG * STAGE_U32;

        uint32_t a[4][4], b[4][2];
        #pragma unroll
        for (int mt = 0; mt < 4; mt++) {
            const int row = wm * 64 + mt * 16 + gid;
            a[mt][0] = Ab[row * GSTRIDE + tig];
            a[mt][1] = Ab[(row + 8) * GSTRIDE + tig];
            a[mt][2] = Ab[row * GSTRIDE + tig + 4];
            a[mt][3] = Ab[(row + 8) * GSTRIDE + tig + 4];
        }
        #pragma unroll
        for (int nt = 0; nt < 4; nt++) {
            const int n = wn * 32 + nt * 8 + gid;
            b[nt][0] = Bb[n * GSTRIDE + tig];
            b[nt][1] = Bb[n * GSTRIDE + tig + 4];
        }
        #pragma unroll
        for (int mt = 0; mt < 4; mt++)
            #pragma unroll
            for (int nt = 0; nt < 4; nt++)
                mma_f16_16x8x16(c[mt][nt], a[mt], b[nt]);
    }

    // epilogue: c0,c1 at (row, col..col+1); c2,c3 at (row+8, col..col+1)
    #pragma unroll
    for (int mt = 0; mt < 4; mt++) {
        const int row = bm + wm * 64 + mt * 16 + gid;
        #pragma unroll
        for (int nt = 0; nt < 4; nt++) {
            const int col = bn + wn * 32 + nt * 8 + tig * 2;
            float u0 = c[mt][nt][0], u1 = c[mt][nt][1];
            float u2 = c[mt][nt][2], u3 = c[mt][nt][3];
            if (BIAS) {
                const float b0v = bias[col], b1v = bias[col + 1];
                u0 += b0v; u1 += b1v; u2 += b0v; u3 += b1v;
            }
            if (SILU) {
                u0 = siluf(u0); u1 = siluf(u1); u2 = siluf(u2); u3 = siluf(u3);
            }
            *(float2*)(C + (size_t)row * CH + col)       = make_float2(u0, u1);
            *(float2*)(C + (size_t)(row + 8) * CH + col) = make_float2(u2, u3);
        }
    }
}

// ===========================================================================
// Stage 3: rmsnorm over 1024 + g_kern scale + silu.
// ===========================================================================
__global__ __launch_bounds__(256) void rmsnorm_silu_kernel(
    const float* __restrict__ gk)
{
    const int token = blockIdx.x;
    const float* p = g_proj + (size_t)token * CH;
    float* o = g_kmax + (size_t)token * CH;

    __shared__ float red[8];
    __shared__ float rbc;
    const int tid  = threadIdx.x;
    const int wid  = tid >> 5;
    const int lane = tid & 31;

    float sq = 0.0f;
    #pragma unroll
    for (int i = tid; i < CH; i += 256) { const float v = p[i]; sq += v * v; }
    #pragma unroll
    for (int d = 16; d > 0; d >>= 1) sq += __shfl_xor_sync(0xffffffffu, sq, d);
    if (lane == 0) red[wid] = sq;
    __syncthreads();
    if (tid == 0) {
        float s = 0.0f;
        #pragma unroll
        for (int i = 0; i < 8; i++) s += red[i];
        rbc = rsqrtf(s * (1.0f / (float)CH) + 1e-6f);
    }
    __syncthreads();
    const float r = rbc;
    #pragma unroll
    for (int i = tid; i < CH; i += 256) {
        o[i] = siluf(gk[i] * p[i] * r);
    }
}

// ===========================================================================
// Stage 4: telephone attention. 1 block/token, 16 warps (1/head).
// Phase A: fused weights kf = kern*(1-frac), kc = kern*frac.
// Phase B: acc += kf*vf + kc*vc. Output written as fp16 (GEMM2 input).
// ===========================================================================
__global__ __launch_bounds__(512) void attn_kernel(const float* __restrict__ x)
{
    const int token = blockIdx.x;
    const int b = token >> 11;
    const int l = token & (SEQLEN - 1);
    const int h    = threadIdx.x >> 5;
    const int lane = threadIdx.x & 31;

    __shared__ float km[NHEAD][KSIZE];
    __shared__ float skf[NHEAD][33];
    __shared__ float skc[NHEAD][33];
    __shared__ int   sfl[NHEAD][33];

    const float* kr = g_kmax + (size_t)token * CH;
    km[h][lane]      = kr[h * KSIZE + lane];
    km[h][lane + 32] = kr[h * KSIZE + lane + 32];

    const float f = g_freq[(size_t)token * NHEAD + h];
    const float p = g_phase[(size_t)token * NHEAD + h];
    const float e = g_expo[token];
    __syncwarp();

    // Phase A: per-sample scalars (lane-parallel)
    for (int s = lane; s < 33; s += 32) {
        const float off = (float)(s - 16);
        const float rel = off * f;
        const float pos = (float)l + rel + p;
        const float validf = (pos >= 0.0f && pos < (float)SEQLEN) ? 1.0f : 0.0f;
        const float pc = fminf(fmaxf(pos, 0.0f), (float)SEQLEN - 1.001f);
        const int   fl = (int)floorf(pc);
        const float frac = pc - (float)fl;
        const float ar = fabsf(rel);
        const float powr = expf(-e * log1pf(ar * (1.0f / (float)SEQLEN)));
        const float idxf = fminf(ar * (1.0f / 256.0f), 1.0f) * 63.0f;
        int i0 = (int)idxf; if (i0 > 62) i0 = 62;
        const float wc = idxf - (float)i0;
        const float kern =
            (km[h][i0] * (1.0f - wc) + km[h][i0 + 1] * wc) * powr * validf;
        skf[h][s] = kern * (1.0f - frac);
        skc[h][s] = kern * frac;
        sfl[h][s] = fl * (CH / 2);
    }
    __syncwarp();

    // Phase B: gather + accumulate. lane covers d=2*lane..2*lane+1.
    const float2* xb = (const float2*)(x + ((size_t)b * SEQLEN) * CH + h * HDIM);
    float acc0 = 0.0f, acc1 = 0.0f;
    #pragma unroll 3
    for (int s = 0; s < 33; s++) {
        const float kf = skf[h][s];
        const float kc = skc[h][s];
        const float2* vfp = xb + sfl[h][s];
        const float2 vf = vfp[lane];
        const float2 vc = vfp[CH / 2 + lane];
        acc0 += kf * vf.x + kc * vc.x;
        acc1 += kf * vf.y + kc * vc.y;
    }

    __half2* hp = (__half2*)(g_ha + (size_t)token * CH + h * HDIM);
    hp[lane] = __floats2half2_rn(acc0, acc1);
}

// ===========================================================================
// launch
// ===========================================================================
extern "C" void kernel_launch(void* const* d_in, const int* in_sizes, int n_in,
                              void* d_out, int out_size)
{
    const float* x      = (const float*)d_in[0];
    const float* w_wave = (const float*)d_in[1];
    const float* b_wave = (const float*)d_in[2];
    const float* g_wave = (const float*)d_in[3];
    const float* w_kern = (const float*)d_in[4];
    const float* b_kern = (const float*)d_in[5];
    const float* g_kern = (const float*)d_in[6];
    const float* w_exp  = (const float*)d_in[7];
    const float* b_exp  = (const float*)d_in[8];
    const float* g_exp  = (const float*)d_in[9];
    const float* w_out  = (const float*)d_in[10];
    float* out = (float*)d_out;

    float *proj_ptr;
    __half *xa_ptr, *ha_ptr, *wk_ptr, *wo_ptr;
    cudaGetSymbolAddress((void**)&proj_ptr, g_proj);
    cudaGetSymbolAddress((void**)&xa_ptr, g_xa);
    cudaGetSymbolAddress((void**)&ha_ptr, g_ha);
    cudaGetSymbolAddress((void**)&wk_ptr, g_wk);
    cudaGetSymbolAddress((void**)&wo_ptr, g_wo);

    cudaFuncSetAttribute(gemm_tc_kernel<true, false>,
                         cudaFuncAttributeMaxDynamicSharedMemorySize, GEMM_SMEM);
    cudaFuncSetAttribute(gemm_tc_kernel<false, true>,
                         cudaFuncAttributeMaxDynamicSharedMemorySize, GEMM_SMEM);

    // convert GEMM operands to fp16
    cvt_f16_kernel<<<(TOKENS * CH / 4 + 255) / 256, 256>>>(x, xa_ptr,
                                                           TOKENS * CH / 4);
    cvt_f16_kernel<<<(CH * CH / 4 + 255) / 256, 256>>>(w_kern, wk_ptr,
                                                       CH * CH / 4);
    cvt_f16_kernel<<<(CH * CH / 4 + 255) / 256, 256>>>(w_out, wo_ptr,
                                                       CH * CH / 4);

    // Stage 1: wave + exp projections (fp32)
    proj_small_kernel<<<TOKENS / 16, 256>>>(x, w_wave, b_wave, g_wave,
                                            w_exp, b_exp, g_exp);

    // Stage 2: kern projection GEMM (+bias) via fp16 mma
    dim3 ggrid(CH / 128, TOKENS / 128);   // (8, 32)
    gemm_tc_kernel<true, false><<<ggrid, 256, GEMM_SMEM>>>(xa_ptr, wk_ptr,
                                                           b_kern, proj_ptr);

    // Stage 3: rmsnorm + silu -> kernel_max
    rmsnorm_silu_kernel<<<TOKENS, 256>>>(g_kern);

    // Stage 4: gather / interpolate / einsum -> hidden (fp16)
    attn_kernel<<<TOKENS, 512>>>(x);

    // Stage 5: output GEMM + silu via fp16 mma
    gemm_tc_kernel<false, true><<<ggrid, 256, GEMM_SMEM>>>(ha_ptr, wo_ptr,
                                                           nullptr, out);
}

// round 6
// speedup vs baseline: 1.6091x; 1.2328x over previous
#include <cuda_runtime.h>
#include <cuda_bf16.h>
#include <cuda_fp16.h>
#include <cstdint>
#include <math.h>

// ---------------------------------------------------------------------------
// TelephoneAttentionND  (B=2, L=2048, C=1024, H=16, D=64, K=64, S=33)
// Stage 1: proj (warp/2-tokens, sync-free) -> freq/phase/expo + x fp16 (g_xa)
// cvt    : w_kern, w_out -> fp16
// Stage 2: kern GEMM [fp16 mma m16n8k16, cp.async] (+bias)  -> g_proj
// Stage 3+4: attn with fused rmsnorm+silu, fp16 gathers     -> g_ha (fp16)
// Stage 5: out GEMM [fp16 mma m16n8k16] + silu              -> d_out
// ---------------------------------------------------------------------------

#define BATCH 2
#define SEQLEN 2048
#define CH 1024
#define NHEAD 16
#define HDIM 64
#define KSIZE 64
#define TOKENS (BATCH * SEQLEN)   // 4096

// scratch (device globals; no allocation allowed)
__device__ float g_freq[TOKENS * NHEAD];
__device__ float g_phase[TOKENS * NHEAD];
__device__ float g_expo[TOKENS];
__device__ float g_proj[(size_t)TOKENS * CH];   // gemm1 out (fp32)
__device__ __half g_xa[(size_t)TOKENS * CH];    // x in fp16
__device__ __half g_ha[(size_t)TOKENS * CH];    // hidden in fp16
__device__ __half g_wk[(size_t)CH * CH];        // w_kern fp16
__device__ __half g_wo[(size_t)CH * CH];        // w_out fp16

__device__ __forceinline__ float siluf(float v) {
    return v / (1.0f + expf(-v));
}

__device__ __forceinline__ void mma_f16_16x8x16(
    float c[4], const uint32_t a[4], const uint32_t b[2])
{
    asm volatile(
        "mma.sync.aligned.m16n8k16.row.col.f32.f16.f16.f32 "
        "{%0, %1, %2, %3}, {%4, %5, %6, %7}, {%8, %9}, {%0, %1, %2, %3};"
        : "+f"(c[0]), "+f"(c[1]), "+f"(c[2]), "+f"(c[3])
        : "r"(a[0]), "r"(a[1]), "r"(a[2]), "r"(a[3]), "r"(b[0]), "r"(b[1]));
}

__device__ __forceinline__ uint32_t smem_u32(const void* p) {
    uint32_t a;
    asm("{ .reg .u64 t; cvta.to.shared.u64 t, %1; cvt.u32.u64 %0, t; }"
        : "=r"(a) : "l"(p));
    return a;
}

__device__ __forceinline__ void cp_async16(uint32_t dst, const void* src) {
    asm volatile("cp.async.ca.shared.global [%0], [%1], 16;"
                 :: "r"(dst), "l"(src));
}
#define CP_COMMIT() asm volatile("cp.async.commit_group;" ::: "memory")
#define CP_WAIT2()  asm volatile("cp.async.wait_group 2;" ::: "memory")

// ===========================================================================
// cvt: fp32 -> fp16 (rn), vectorized (4 elems/thread)
// ===========================================================================
__global__ __launch_bounds__(256) void cvt_f16_kernel(
    const float* __restrict__ in, __half* __restrict__ out, int n4)
{
    const int idx = blockIdx.x * 256 + threadIdx.x;
    if (idx < n4) {
        const float4 v = ((const float4*)in)[idx];
        __half2 h0 = __floats2half2_rn(v.x, v.y);
        __half2 h1 = __floats2half2_rn(v.z, v.w);
        uint2 o;
        o.x = *(uint32_t*)&h0;
        o.y = *(uint32_t*)&h1;
        ((uint2*)out)[idx] = o;
    }
}

// ===========================================================================
// Stage 1: wave+exp projection, warp-per-2-tokens, no inner syncs.
// grid = 256 blocks x 256 threads; warp handles tokens (blk*16 + wid*2, +1).
// x slices held in registers (interleaved float4 map, coalesced); weight
// rows streamed with coalesced LDG.128; shfl butterfly reductions.
// Side effect: writes x as fp16 to g_xa.
// ===========================================================================
__global__ __launch_bounds__(256) void proj_small_kernel(
    const float* __restrict__ x,
    const float* __restrict__ w_wave, const float* __restrict__ b_wave,
    const float* __restrict__ g_wave,
    const float* __restrict__ w_exp, const float* __restrict__ b_exp,
    const float* __restrict__ g_exp)
{
    const int tid  = threadIdx.x;
    const int wid  = tid >> 5;
    const int lane = tid & 31;
    const int tok0 = blockIdx.x * 16 + wid * 2;

    __shared__ float po[16][34];

    // load x slices (2 tokens) into regs; emit fp16 copy
    float4 xr0[8], xr1[8];
    {
        const float* x0 = x + (size_t)tok0 * CH;
        const float* x1 = x0 + CH;
        uint2* xa0 = (uint2*)(g_xa + (size_t)tok0 * CH);
        uint2* xa1 = (uint2*)(g_xa + (size_t)(tok0 + 1) * CH);
        #pragma unroll
        for (int j = 0; j < 8; j++) {
            xr0[j] = *(const float4*)(x0 + j * 128 + lane * 4);
            xr1[j] = *(const float4*)(x1 + j * 128 + lane * 4);
            __half2 a0 = __floats2half2_rn(xr0[j].x, xr0[j].y);
            __half2 a1 = __floats2half2_rn(xr0[j].z, xr0[j].w);
            __half2 b0 = __floats2half2_rn(xr1[j].x, xr1[j].y);
            __half2 b1 = __floats2half2_rn(xr1[j].z, xr1[j].w);
            uint2 pa, pb;
            pa.x = *(uint32_t*)&a0; pa.y = *(uint32_t*)&a1;
            pb.x = *(uint32_t*)&b0; pb.y = *(uint32_t*)&b1;
            xa0[j * 32 + lane] = pa;
            xa1[j * 32 + lane] = pb;
        }
    }

    // 33 outputs: dot over K=1024, warp-reduced
    for (int o = 0; o < 33; o++) {
        const float* wrow = (o < 32) ? (w_wave + (size_t)o * CH) : w_exp;
        float d0 = 0.f, d1 = 0.f;
        #pragma unroll
        for (int j = 0; j < 8; j++) {
            const float4 w4 = *(const float4*)(wrow + j * 128 + lane * 4);
            d0 += xr0[j].x * w4.x + xr0[j].y * w4.y
                + xr0[j].z * w4.z + xr0[j].w * w4.w;
            d1 += xr1[j].x * w4.x + xr1[j].y * w4.y
                + xr1[j].z * w4.z + xr1[j].w * w4.w;
        }
        #pragma unroll
        for (int d = 16; d > 0; d >>= 1) {
            d0 += __shfl_xor_sync(0xffffffffu, d0, d);
            d1 += __shfl_xor_sync(0xffffffffu, d1, d);
        }
        if (lane == 0) {
            const float bv = (o < 32) ? b_wave[o] : b_exp[0];
            po[wid * 2][o]     = d0 + bv;
            po[wid * 2 + 1][o] = d1 + bv;
        }
    }
    __syncthreads();

    // activations: warp wid handles tokens wid and wid+8 (within block)
    #pragma unroll
    for (int it = 0; it < 2; it++) {
        const int tk = wid + it * 8;
        const int gtok = blockIdx.x * 16 + tk;
        float v = po[tk][lane];
        float sq = v * v;
        #pragma unroll
        for (int d = 16; d > 0; d >>= 1) sq += __shfl_xor_sync(0xffffffffu, sq, d);
        const float r = rsqrtf(sq * (1.0f / 32.0f) + 1e-6f);
        const float sil = siluf(g_wave[lane] * v * r);
        if (lane < 16) {
            g_freq[(size_t)gtok * NHEAD + lane] = 15.0f / (1.0f + expf(-sil)) + 1.0f;
        } else {
            g_phase[(size_t)gtok * NHEAD + (lane - 16)] = tanhf(sil) * 16.0f;
        }
        if (lane == 0) {
            const float ve = po[tk][32];
            const float y = g_exp[0] * ve * rsqrtf(ve * ve + 1e-6f);
            g_expo[gtok] = (1.0f / (1.0f + expf(-y))) * 3.5f + 0.5f;
        }
    }
}

// ===========================================================================
// Stages 2 & 5: fp16 mma.sync m16n8k16 GEMM with cp.async 4-stage pipeline.
// C[M,N] = A[M,K]*B[N,K]^T, fp32 accumulate. Operands pre-converted fp16.
// 128x128 CTA tile, 8 warps (2x4), warp = 64x32 via 4x4 m16n8k16.
// smem: half2 words, row stride 12 u32 (8 used + pad) -> conflict-free LDS.
// ===========================================================================
#define GSTRIDE 12                                     // u32 per row
#define STG 4
#define STAGE_U32 (128 * GSTRIDE)                      // 1536 u32 per matrix stage
#define GEMM_SMEM (STG * STAGE_U32 * 2 * 4)            // 49152 bytes

template <bool BIAS, bool SILU>
__global__ __launch_bounds__(256) void gemm_tc_kernel(
    const __half* __restrict__ A, const __half* __restrict__ B,
    const float* __restrict__ bias, float* __restrict__ C)
{
    extern __shared__ uint32_t smem32[];
    const uint32_t smem_base = smem_u32(smem32);

    const int tid  = threadIdx.x;
    const int wid  = tid >> 5;
    const int lane = tid & 31;
    const int gid  = lane >> 2;     // groupID 0..7
    const int tig  = lane & 3;      // thread-in-group 0..3
    const int wm   = wid & 1;       // warp row (0..1) -> 64 rows each
    const int wn   = wid >> 1;      // warp col (0..3) -> 32 cols each

    const int bm = blockIdx.y * 128;
    const int bn = blockIdx.x * 128;

    // cp.async mapping: 128 rows x 16 halves per matrix stage; 256 x 16B.
    const int r0  = tid >> 1;            // 0..127
    const int hr0 = (tid & 1) * 8;       // half offset within row (0 or 8)
    const uint32_t a_s = smem_base + (uint32_t)(r0 * GSTRIDE + (hr0 >> 1)) * 4;
    const uint32_t b_s = a_s + STG * STAGE_U32 * 4;
    const __half* gA0 = A + (size_t)(bm + r0) * CH + hr0;
    const __half* gB0 = B + (size_t)(bn + r0) * CH + hr0;

    float c[4][4][4];
    #pragma unroll
    for (int mt = 0; mt < 4; mt++)
        #pragma unroll
        for (int nt = 0; nt < 4; nt++)
            #pragma unroll
            for (int j = 0; j < 4; j++) c[mt][nt][j] = 0.0f;

    const int NCHUNK = CH / 16;   // 64

    // prologue: stages 0..2
    #pragma unroll
    for (int s = 0; s < STG - 1; s++) {
        const uint32_t so = (uint32_t)(s * STAGE_U32) * 4;
        cp_async16(a_s + so, gA0 + s * 16);
        cp_async16(b_s + so, gB0 + s * 16);
        CP_COMMIT();
    }

    for (int kc = 0; kc < NCHUNK; kc++) {
        CP_WAIT2();
        __syncthreads();

        if (kc + STG - 1 < NCHUNK) {
            const uint32_t so = (uint32_t)(((kc + STG - 1) & (STG - 1)) * STAGE_U32) * 4;
            cp_async16(a_s + so, gA0 + (kc + STG - 1) * 16);
            cp_async16(b_s + so, gB0 + (kc + STG - 1) * 16);
        }
        CP_COMMIT();

        const uint32_t* Ab = smem32 + (kc & (STG - 1)) * STAGE_U32;
        const uint32_t* Bb = Ab + STG * STAGE_U32;

        uint32_t a[4][4], b[4][2];
        #pragma unroll
        for (int mt = 0; mt < 4; mt++) {
            const int row = wm * 64 + mt * 16 + gid;
            a[mt][0] = Ab[row * GSTRIDE + tig];
            a[mt][1] = Ab[(row + 8) * GSTRIDE + tig];
            a[mt][2] = Ab[row * GSTRIDE + tig + 4];
            a[mt][3] = Ab[(row + 8) * GSTRIDE + tig + 4];
        }
        #pragma unroll
        for (int nt = 0; nt < 4; nt++) {
            const int n = wn * 32 + nt * 8 + gid;
            b[nt][0] = Bb[n * GSTRIDE + tig];
            b[nt][1] = Bb[n * GSTRIDE + tig + 4];
        }
        #pragma unroll
        for (int mt = 0; mt < 4; mt++)
            #pragma unroll
            for (int nt = 0; nt < 4; nt++)
                mma_f16_16x8x16(c[mt][nt], a[mt], b[nt]);
    }

    // epilogue: c0,c1 at (row, col..col+1); c2,c3 at (row+8, col..col+1)
    #pragma unroll
    for (int mt = 0; mt < 4; mt++) {
        const int row = bm + wm * 64 + mt * 16 + gid;
        #pragma unroll
        for (int nt = 0; nt < 4; nt++) {
            const int col = bn + wn * 32 + nt * 8 + tig * 2;
            float u0 = c[mt][nt][0], u1 = c[mt][nt][1];
            float u2 = c[mt][nt][2], u3 = c[mt][nt][3];
            if (BIAS) {
                const float b0v = bias[col], b1v = bias[col + 1];
                u0 += b0v; u1 += b1v; u2 += b0v; u3 += b1v;
            }
            if (SILU) {
                u0 = siluf(u0); u1 = siluf(u1); u2 = siluf(u2); u3 = siluf(u3);
            }
            *(float2*)(C + (size_t)row * CH + col)       = make_float2(u0, u1);
            *(float2*)(C + (size_t)(row + 8) * CH + col) = make_float2(u2, u3);
        }
    }
}

// ===========================================================================
// Stages 3+4 fused: rmsnorm+silu (from g_proj) then telephone attention.
// 1 block/token, 512 threads. km[h] is written by warp h -> warp-local sync.
// Phase B gathers fp16 x from g_xa. Output fp16 to g_ha.
// ===========================================================================
__global__ __launch_bounds__(512) void attn_kernel(
    const __half* __restrict__ xa, const float* __restrict__ gk)
{
    const int token = blockIdx.x;
    const int b = token >> 11;
    const int l = token & (SEQLEN - 1);
    const int tid  = threadIdx.x;
    const int h    = tid >> 5;
    const int lane = tid & 31;

    __shared__ float km[NHEAD][KSIZE];
    __shared__ float red[16];
    __shared__ float rbc;
    __shared__ float skf[NHEAD][33];
    __shared__ float skc[NHEAD][33];
    __shared__ int   sfl[NHEAD][33];

    // fused rmsnorm: sumsq over g_proj row
    const float2 pv = ((const float2*)(g_proj + (size_t)token * CH))[tid];
    float sq = pv.x * pv.x + pv.y * pv.y;
    #pragma unroll
    for (int d = 16; d > 0; d >>= 1) sq += __shfl_xor_sync(0xffffffffu, sq, d);
    if (lane == 0) red[h] = sq;
    __syncthreads();
    if (tid == 0) {
        float s = 0.f;
        #pragma unroll
        for (int i = 0; i < 16; i++) s += red[i];
        rbc = rsqrtf(s * (1.0f / (float)CH) + 1e-6f);
    }
    __syncthreads();
    {
        const float r = rbc;
        float* kmf = &km[0][0];
        kmf[2 * tid]     = siluf(gk[2 * tid] * pv.x * r);
        kmf[2 * tid + 1] = siluf(gk[2 * tid + 1] * pv.y * r);
    }
    // km[h][0..63] is written exactly by warp h -> warp sync suffices
    __syncwarp();

    const float f = g_freq[(size_t)token * NHEAD + h];
    const float p = g_phase[(size_t)token * NHEAD + h];
    const float e = g_expo[token];

    // Phase A: per-sample scalars (lane-parallel)
    for (int s = lane; s < 33; s += 32) {
        const float off = (float)(s - 16);
        const float rel = off * f;
        const float pos = (float)l + rel + p;
        const float validf = (pos >= 0.0f && pos < (float)SEQLEN) ? 1.0f : 0.0f;
        const float pc = fminf(fmaxf(pos, 0.0f), (float)SEQLEN - 1.001f);
        const int   fl = (int)floorf(pc);
        const float frac = pc - (float)fl;
        const float ar = fabsf(rel);
        const float powr = expf(-e * log1pf(ar * (1.0f / (float)SEQLEN)));
        const float idxf = fminf(ar * (1.0f / 256.0f), 1.0f) * 63.0f;
        int i0 = (int)idxf; if (i0 > 62) i0 = 62;
        const float wc = idxf - (float)i0;
        const float kern =
            (km[h][i0] * (1.0f - wc) + km[h][i0 + 1] * wc) * powr * validf;
        skf[h][s] = kern * (1.0f - frac);
        skc[h][s] = kern * frac;
        sfl[h][s] = fl * (CH / 2);
    }
    __syncwarp();

    // Phase B: fp16 gather + accumulate. lane covers d=2*lane..2*lane+1.
    const __half2* xb = (const __half2*)(xa + ((size_t)b * SEQLEN) * CH + h * HDIM);
    float acc0 = 0.0f, acc1 = 0.0f;
    #pragma unroll 3
    for (int s = 0; s < 33; s++) {
        const float kf = skf[h][s];
        const float kc = skc[h][s];
        const __half2 hf = xb[sfl[h][s] + lane];
        const __half2 hc = xb[sfl[h][s] + (CH / 2) + lane];
        const float2 vf = __half22float2(hf);
        const float2 vc = __half22float2(hc);
        acc0 += kf * vf.x + kc * vc.x;
        acc1 += kf * vf.y + kc * vc.y;
    }

    __half2* hp = (__half2*)(g_ha + (size_t)token * CH + h * HDIM);
    hp[lane] = __floats2half2_rn(acc0, acc1);
}

// ===========================================================================
// launch
// ===========================================================================
extern "C" void kernel_launch(void* const* d_in, const int* in_sizes, int n_in,
                              void* d_out, int out_size)
{
    const float* x      = (const float*)d_in[0];
    const float* w_wave = (const float*)d_in[1];
    const float* b_wave = (const float*)d_in[2];
    const float* g_wave = (const float*)d_in[3];
    const float* w_kern = (const float*)d_in[4];
    const float* b_kern = (const float*)d_in[5];
    const float* g_kern = (const float*)d_in[6];
    const float* w_exp  = (const float*)d_in[7];
    const float* b_exp  = (const float*)d_in[8];
    const float* g_exp  = (const float*)d_in[9];
    const float* w_out  = (const float*)d_in[10];
    float* out = (float*)d_out;

    float *proj_ptr;
    __half *xa_ptr, *ha_ptr, *wk_ptr, *wo_ptr;
    cudaGetSymbolAddress((void**)&proj_ptr, g_proj);
    cudaGetSymbolAddress((void**)&xa_ptr, g_xa);
    cudaGetSymbolAddress((void**)&ha_ptr, g_ha);
    cudaGetSymbolAddress((void**)&wk_ptr, g_wk);
    cudaGetSymbolAddress((void**)&wo_ptr, g_wo);

    cudaFuncSetAttribute(gemm_tc_kernel<true, false>,
                         cudaFuncAttributeMaxDynamicSharedMemorySize, GEMM_SMEM);
    cudaFuncSetAttribute(gemm_tc_kernel<false, true>,
                         cudaFuncAttributeMaxDynamicSharedMemorySize, GEMM_SMEM);

    // Stage 1: wave + exp projections (fp32) + x -> fp16
    proj_small_kernel<<<TOKENS / 16, 256>>>(x, w_wave, b_wave, g_wave,
                                            w_exp, b_exp, g_exp);

    // convert weights to fp16
    cvt_f16_kernel<<<(CH * CH / 4 + 255) / 256, 256>>>(w_kern, wk_ptr,
                                                       CH * CH / 4);
    cvt_f16_kernel<<<(CH * CH / 4 + 255) / 256, 256>>>(w_out, wo_ptr,
                                                       CH * CH / 4);

    // Stage 2: kern projection GEMM (+bias) via fp16 mma
    dim3 ggrid(CH / 128, TOKENS / 128);   // (8, 32)
    gemm_tc_kernel<true, false><<<ggrid, 256, GEMM_SMEM>>>(xa_ptr, wk_ptr,
                                                           b_kern, proj_ptr);

    // Stages 3+4: fused rmsnorm + attention -> hidden (fp16)
    attn_kernel<<<TOKENS, 512>>>(xa_ptr, g_kern);

    // Stage 5: output GEMM + silu via fp16 mma
    gemm_tc_kernel<false, true><<<ggrid, 256, GEMM_SMEM>>>(ha_ptr, wo_ptr,
                                                           nullptr, out);
}

// round 7
// speedup vs baseline: 1.8836x; 1.1706x over previous
#include <cuda_runtime.h>
#include <cuda_bf16.h>
#include <cuda_fp16.h>
#include <cstdint>
#include <math.h>

// ---------------------------------------------------------------------------
// TelephoneAttentionND  (B=2, L=2048, C=1024, H=16, D=64, K=64, S=33)
// Stage 1: proj (warp/2-tokens, sync-free) -> freq/phase/expo + x fp16 (g_xa)
// cvt    : w_kern, w_out -> fp16
// Stage 2: kern GEMM [fp16 mma, ldmatrix, BK=32, cp.async] (+bias) -> g_proj
// Stage 3+4: attn with fused rmsnorm+silu, fp16 gathers            -> g_ha
// Stage 5: out GEMM [fp16 mma] + silu                              -> d_out
// ---------------------------------------------------------------------------

#define BATCH 2
#define SEQLEN 2048
#define CH 1024
#define NHEAD 16
#define HDIM 64
#define KSIZE 64
#define TOKENS (BATCH * SEQLEN)   // 4096

// scratch (device globals; no allocation allowed)
__device__ float g_freq[TOKENS * NHEAD];
__device__ float g_phase[TOKENS * NHEAD];
__device__ float g_expo[TOKENS];
__device__ float g_proj[(size_t)TOKENS * CH];   // gemm1 out (fp32)
__device__ __half g_xa[(size_t)TOKENS * CH];    // x in fp16
__device__ __half g_ha[(size_t)TOKENS * CH];    // hidden in fp16
__device__ __half g_wk[(size_t)CH * CH];        // w_kern fp16
__device__ __half g_wo[(size_t)CH * CH];        // w_out fp16

__device__ __forceinline__ float siluf(float v) {
    return v / (1.0f + expf(-v));
}

__device__ __forceinline__ void mma_f16_16x8x16(
    float c[4], const uint32_t a[4], uint32_t b0, uint32_t b1)
{
    asm volatile(
        "mma.sync.aligned.m16n8k16.row.col.f32.f16.f16.f32 "
        "{%0, %1, %2, %3}, {%4, %5, %6, %7}, {%8, %9}, {%0, %1, %2, %3};"
        : "+f"(c[0]), "+f"(c[1]), "+f"(c[2]), "+f"(c[3])
        : "r"(a[0]), "r"(a[1]), "r"(a[2]), "r"(a[3]), "r"(b0), "r"(b1));
}

__device__ __forceinline__ void ldsm_x4(uint32_t r[4], uint32_t addr) {
    asm volatile(
        "ldmatrix.sync.aligned.m8n8.x4.shared.b16 {%0, %1, %2, %3}, [%4];"
        : "=r"(r[0]), "=r"(r[1]), "=r"(r[2]), "=r"(r[3]) : "r"(addr));
}

__device__ __forceinline__ uint32_t smem_u32(const void* p) {
    uint32_t a;
    asm("{ .reg .u64 t; cvta.to.shared.u64 t, %1; cvt.u32.u64 %0, t; }"
        : "=r"(a) : "l"(p));
    return a;
}

__device__ __forceinline__ void cp_async16(uint32_t dst, const void* src) {
    asm volatile("cp.async.ca.shared.global [%0], [%1], 16;"
                 :: "r"(dst), "l"(src));
}
#define CP_COMMIT() asm volatile("cp.async.commit_group;" ::: "memory")
#define CP_WAIT2()  asm volatile("cp.async.wait_group 2;" ::: "memory")

// ===========================================================================
// cvt: fp32 -> fp16 (rn), vectorized (4 elems/thread)
// ===========================================================================
__global__ __launch_bounds__(256) void cvt_f16_kernel(
    const float* __restrict__ in, __half* __restrict__ out, int n4)
{
    const int idx = blockIdx.x * 256 + threadIdx.x;
    if (idx < n4) {
        const float4 v = ((const float4*)in)[idx];
        __half2 h0 = __floats2half2_rn(v.x, v.y);
        __half2 h1 = __floats2half2_rn(v.z, v.w);
        uint2 o;
        o.x = *(uint32_t*)&h0;
        o.y = *(uint32_t*)&h1;
        ((uint2*)out)[idx] = o;
    }
}

// ===========================================================================
// Stage 1: wave+exp projection, warp-per-2-tokens, no inner syncs.
// Side effect: writes x as fp16 to g_xa.
// ===========================================================================
__global__ __launch_bounds__(256) void proj_small_kernel(
    const float* __restrict__ x,
    const float* __restrict__ w_wave, const float* __restrict__ b_wave,
    const float* __restrict__ g_wave,
    const float* __restrict__ w_exp, const float* __restrict__ b_exp,
    const float* __restrict__ g_exp)
{
    const int tid  = threadIdx.x;
    const int wid  = tid >> 5;
    const int lane = tid & 31;
    const int tok0 = blockIdx.x * 16 + wid * 2;

    __shared__ float po[16][34];

    float4 xr0[8], xr1[8];
    {
        const float* x0 = x + (size_t)tok0 * CH;
        const float* x1 = x0 + CH;
        uint2* xa0 = (uint2*)(g_xa + (size_t)tok0 * CH);
        uint2* xa1 = (uint2*)(g_xa + (size_t)(tok0 + 1) * CH);
        #pragma unroll
        for (int j = 0; j < 8; j++) {
            xr0[j] = *(const float4*)(x0 + j * 128 + lane * 4);
            xr1[j] = *(const float4*)(x1 + j * 128 + lane * 4);
            __half2 a0 = __floats2half2_rn(xr0[j].x, xr0[j].y);
            __half2 a1 = __floats2half2_rn(xr0[j].z, xr0[j].w);
            __half2 b0 = __floats2half2_rn(xr1[j].x, xr1[j].y);
            __half2 b1 = __floats2half2_rn(xr1[j].z, xr1[j].w);
            uint2 pa, pb;
            pa.x = *(uint32_t*)&a0; pa.y = *(uint32_t*)&a1;
            pb.x = *(uint32_t*)&b0; pb.y = *(uint32_t*)&b1;
            xa0[j * 32 + lane] = pa;
            xa1[j * 32 + lane] = pb;
        }
    }

    for (int o = 0; o < 33; o++) {
        const float* wrow = (o < 32) ? (w_wave + (size_t)o * CH) : w_exp;
        float d0 = 0.f, d1 = 0.f;
        #pragma unroll
        for (int j = 0; j < 8; j++) {
            const float4 w4 = *(const float4*)(wrow + j * 128 + lane * 4);
            d0 += xr0[j].x * w4.x + xr0[j].y * w4.y
                + xr0[j].z * w4.z + xr0[j].w * w4.w;
            d1 += xr1[j].x * w4.x + xr1[j].y * w4.y
                + xr1[j].z * w4.z + xr1[j].w * w4.w;
        }
        #pragma unroll
        for (int d = 16; d > 0; d >>= 1) {
            d0 += __shfl_xor_sync(0xffffffffu, d0, d);
            d1 += __shfl_xor_sync(0xffffffffu, d1, d);
        }
        if (lane == 0) {
            const float bv = (o < 32) ? b_wave[o] : b_exp[0];
            po[wid * 2][o]     = d0 + bv;
            po[wid * 2 + 1][o] = d1 + bv;
        }
    }
    __syncthreads();

    #pragma unroll
    for (int it = 0; it < 2; it++) {
        const int tk = wid + it * 8;
        const int gtok = blockIdx.x * 16 + tk;
        float v = po[tk][lane];
        float sq = v * v;
        #pragma unroll
        for (int d = 16; d > 0; d >>= 1) sq += __shfl_xor_sync(0xffffffffu, sq, d);
        const float r = rsqrtf(sq * (1.0f / 32.0f) + 1e-6f);
        const float sil = siluf(g_wave[lane] * v * r);
        if (lane < 16) {
            g_freq[(size_t)gtok * NHEAD + lane] = 15.0f / (1.0f + expf(-sil)) + 1.0f;
        } else {
            g_phase[(size_t)gtok * NHEAD + (lane - 16)] = tanhf(sil) * 16.0f;
        }
        if (lane == 0) {
            const float ve = po[tk][32];
            const float y = g_exp[0] * ve * rsqrtf(ve * ve + 1e-6f);
            g_expo[gtok] = (1.0f / (1.0f + expf(-y))) * 3.5f + 0.5f;
        }
    }
}

// ===========================================================================
// Stages 2 & 5: fp16 mma m16n8k16 GEMM, ldmatrix fragments, BK=32,
// cp.async 4-stage pipeline. C[M,N] = A[M,K]*B[N,K]^T, fp32 accumulate.
// 128x128 CTA tile, 8 warps (2x4), warp = 64x32.
// smem rows: 32 halves (16 u32) + 4 pad = stride 20 u32 -> LDSM conflict-free.
// ===========================================================================
#define GSTRIDE 20                                     // u32 per row
#define STG 4
#define STAGE_U32 (128 * GSTRIDE)                      // 2560 u32 per matrix stage
#define GEMM_SMEM (STG * STAGE_U32 * 2 * 4)            // 81920 bytes

template <bool BIAS, bool SILU>
__global__ __launch_bounds__(256) void gemm_tc_kernel(
    const __half* __restrict__ A, const __half* __restrict__ B,
    const float* __restrict__ bias, float* __restrict__ C)
{
    extern __shared__ uint32_t smem32[];
    const uint32_t smem_base = smem_u32(smem32);
    const uint32_t BOFF = STG * STAGE_U32 * 4;   // byte offset of B region

    const int tid  = threadIdx.x;
    const int wid  = tid >> 5;
    const int lane = tid & 31;
    const int gid  = lane >> 2;     // groupID 0..7
    const int tig  = lane & 3;      // thread-in-group 0..3
    const int wm   = wid & 1;       // warp row (0..1) -> 64 rows each
    const int wn   = wid >> 1;      // warp col (0..3) -> 32 cols each

    const int bm = blockIdx.y * 128;
    const int bn = blockIdx.x * 128;

    // cp.async mapping: per stage per matrix 128 rows x 64B = 512 x 16B.
    // thread covers rows (tid>>2) and (tid>>2)+64, 16B chunk c = tid&3.
    const int crow = tid >> 2;
    const int cc   = tid & 3;
    const uint32_t sa0 = smem_base + (uint32_t)(crow * GSTRIDE + cc * 4) * 4;
    const uint32_t sa1 = smem_base + (uint32_t)((crow + 64) * GSTRIDE + cc * 4) * 4;
    const __half* gA0 = A + (size_t)(bm + crow) * CH + cc * 8;
    const __half* gA1 = A + (size_t)(bm + crow + 64) * CH + cc * 8;
    const __half* gB0 = B + (size_t)(bn + crow) * CH + cc * 8;
    const __half* gB1 = B + (size_t)(bn + crow + 64) * CH + cc * 8;

    // ldmatrix per-thread addresses (byte), before stage/ksub offsets.
    // A x4: m0<-t0-7 rows0-7 k0-7 | m1<-t8-15 rows8-15 k0-7
    //       m2<-t16-23 rows0-7 k8-15 | m3<-t24-31 rows8-15 k8-15
    const int rA = (lane & 7) + ((lane >> 3) & 1) * 8;
    const int kA = (lane >> 4) * 4;                      // u32
    uint32_t a_addr[4];
    #pragma unroll
    for (int mt = 0; mt < 4; mt++) {
        const int row = wm * 64 + mt * 16 + rA;
        a_addr[mt] = smem_base + (uint32_t)(row * GSTRIDE + kA) * 4;
    }
    // B x4 (covers nt pair): m0<-t0-7 rows0-7 k0-7 | m1<-t8-15 rows0-7 k8-15
    //       m2<-t16-23 rows8-15 k0-7 | m3<-t24-31 rows8-15 k8-15
    const int rB = (lane & 7) + ((lane >> 4) << 3);
    const int kB = ((lane >> 3) & 1) * 4;                // u32
    uint32_t b_addr[2];
    #pragma unroll
    for (int pr = 0; pr < 2; pr++) {
        const int row = wn * 32 + pr * 16 + rB;
        b_addr[pr] = smem_base + BOFF + (uint32_t)(row * GSTRIDE + kB) * 4;
    }

    float c[4][4][4];
    #pragma unroll
    for (int mt = 0; mt < 4; mt++)
        #pragma unroll
        for (int nt = 0; nt < 4; nt++)
            #pragma unroll
            for (int j = 0; j < 4; j++) c[mt][nt][j] = 0.0f;

    const int NCHUNK = CH / 32;   // 32

    // prologue: stages 0..2
    #pragma unroll
    for (int s = 0; s < STG - 1; s++) {
        const uint32_t so = (uint32_t)(s * STAGE_U32) * 4;
        cp_async16(sa0 + so, gA0 + s * 32);
        cp_async16(sa1 + so, gA1 + s * 32);
        cp_async16(sa0 + so + BOFF, gB0 + s * 32);
        cp_async16(sa1 + so + BOFF, gB1 + s * 32);
        CP_COMMIT();
    }

    for (int kc = 0; kc < NCHUNK; kc++) {
        CP_WAIT2();
        __syncthreads();

        if (kc + STG - 1 < NCHUNK) {
            const uint32_t so = (uint32_t)(((kc + STG - 1) & (STG - 1)) * STAGE_U32) * 4;
            const int k0 = (kc + STG - 1) * 32;
            cp_async16(sa0 + so, gA0 + k0);
            cp_async16(sa1 + so, gA1 + k0);
            cp_async16(sa0 + so + BOFF, gB0 + k0);
            cp_async16(sa1 + so + BOFF, gB1 + k0);
        }
        CP_COMMIT();

        const uint32_t soff = (uint32_t)((kc & (STG - 1)) * STAGE_U32) * 4;

        #pragma unroll
        for (int ksub = 0; ksub < 2; ksub++) {
            const uint32_t ko = soff + ksub * 32;   // 8 u32 = 32B per ksub
            uint32_t a[4][4], b[2][4];
            #pragma unroll
            for (int mt = 0; mt < 4; mt++) ldsm_x4(a[mt], a_addr[mt] + ko);
            #pragma unroll
            for (int pr = 0; pr < 2; pr++) ldsm_x4(b[pr], b_addr[pr] + ko);
            #pragma unroll
            for (int mt = 0; mt < 4; mt++) {
                #pragma unroll
                for (int nt = 0; nt < 4; nt++)
                    mma_f16_16x8x16(c[mt][nt], a[mt],
                                    b[nt >> 1][(nt & 1) * 2],
                                    b[nt >> 1][(nt & 1) * 2 + 1]);
            }
        }
    }

    // epilogue: c0,c1 at (row, col..col+1); c2,c3 at (row+8, col..col+1)
    #pragma unroll
    for (int mt = 0; mt < 4; mt++) {
        const int row = bm + wm * 64 + mt * 16 + gid;
        #pragma unroll
        for (int nt = 0; nt < 4; nt++) {
            const int col = bn + wn * 32 + nt * 8 + tig * 2;
            float u0 = c[mt][nt][0], u1 = c[mt][nt][1];
            float u2 = c[mt][nt][2], u3 = c[mt][nt][3];
            if (BIAS) {
                const float b0v = bias[col], b1v = bias[col + 1];
                u0 += b0v; u1 += b1v; u2 += b0v; u3 += b1v;
            }
            if (SILU) {
                u0 = siluf(u0); u1 = siluf(u1); u2 = siluf(u2); u3 = siluf(u3);
            }
            *(float2*)(C + (size_t)row * CH + col)       = make_float2(u0, u1);
            *(float2*)(C + (size_t)(row + 8) * CH + col) = make_float2(u2, u3);
        }
    }
}

// ===========================================================================
// Stages 3+4 fused: rmsnorm+silu (from g_proj) then telephone attention.
// 1 block/token, 512 threads. Phase B gathers fp16 from g_xa -> fp16 g_ha.
// ===========================================================================
__global__ __launch_bounds__(512) void attn_kernel(
    const __half* __restrict__ xa, const float* __restrict__ gk)
{
    const int token = blockIdx.x;
    const int b = token >> 11;
    const int l = token & (SEQLEN - 1);
    const int tid  = threadIdx.x;
    const int h    = tid >> 5;
    const int lane = tid & 31;

    __shared__ float km[NHEAD][KSIZE];
    __shared__ float red[16];
    __shared__ float rbc;
    __shared__ float skf[NHEAD][33];
    __shared__ float skc[NHEAD][33];
    __shared__ int   sfl[NHEAD][33];

    const float2 pv = ((const float2*)(g_proj + (size_t)token * CH))[tid];
    float sq = pv.x * pv.x + pv.y * pv.y;
    #pragma unroll
    for (int d = 16; d > 0; d >>= 1) sq += __shfl_xor_sync(0xffffffffu, sq, d);
    if (lane == 0) red[h] = sq;
    __syncthreads();
    if (tid == 0) {
        float s = 0.f;
        #pragma unroll
        for (int i = 0; i < 16; i++) s += red[i];
        rbc = rsqrtf(s * (1.0f / (float)CH) + 1e-6f);
    }
    __syncthreads();
    {
        const float r = rbc;
        float* kmf = &km[0][0];
        kmf[2 * tid]     = siluf(gk[2 * tid] * pv.x * r);
        kmf[2 * tid + 1] = siluf(gk[2 * tid + 1] * pv.y * r);
    }
    __syncwarp();

    const float f = g_freq[(size_t)token * NHEAD + h];
    const float p = g_phase[(size_t)token * NHEAD + h];
    const float e = g_expo[token];

    for (int s = lane; s < 33; s += 32) {
        const float off = (float)(s - 16);
        const float rel = off * f;
        const float pos = (float)l + rel + p;
        const float validf = (pos >= 0.0f && pos < (float)SEQLEN) ? 1.0f : 0.0f;
        const float pc = fminf(fmaxf(pos, 0.0f), (float)SEQLEN - 1.001f);
        const int   fl = (int)floorf(pc);
        const float frac = pc - (float)fl;
        const float ar = fabsf(rel);
        const float powr = expf(-e * log1pf(ar * (1.0f / (float)SEQLEN)));
        const float idxf = fminf(ar * (1.0f / 256.0f), 1.0f) * 63.0f;
        int i0 = (int)idxf; if (i0 > 62) i0 = 62;
        const float wc = idxf - (float)i0;
        const float kern =
            (km[h][i0] * (1.0f - wc) + km[h][i0 + 1] * wc) * powr * validf;
        skf[h][s] = kern * (1.0f - frac);
        skc[h][s] = kern * frac;
        sfl[h][s] = fl * (CH / 2);
    }
    __syncwarp();

    const __half2* xb = (const __half2*)(xa + ((size_t)b * SEQLEN) * CH + h * HDIM);
    float acc0 = 0.0f, acc1 = 0.0f;
    #pragma unroll 3
    for (int s = 0; s < 33; s++) {
        const float kf = skf[h][s];
        const float kc = skc[h][s];
        const __half2 hf = xb[sfl[h][s] + lane];
        const __half2 hc = xb[sfl[h][s] + (CH / 2) + lane];
        const float2 vf = __half22float2(hf);
        const float2 vc = __half22float2(hc);
        acc0 += kf * vf.x + kc * vc.x;
        acc1 += kf * vf.y + kc * vc.y;
    }

    __half2* hp = (__half2*)(g_ha + (size_t)token * CH + h * HDIM);
    hp[lane] = __floats2half2_rn(acc0, acc1);
}

// ===========================================================================
// launch
// ===========================================================================
extern "C" void kernel_launch(void* const* d_in, const int* in_sizes, int n_in,
                              void* d_out, int out_size)
{
    const float* x      = (const float*)d_in[0];
    const float* w_wave = (const float*)d_in[1];
    const float* b_wave = (const float*)d_in[2];
    const float* g_wave = (const float*)d_in[3];
    const float* w_kern = (const float*)d_in[4];
    const float* b_kern = (const float*)d_in[5];
    const float* g_kern = (const float*)d_in[6];
    const float* w_exp  = (const float*)d_in[7];
    const float* b_exp  = (const float*)d_in[8];
    const float* g_exp  = (const float*)d_in[9];
    const float* w_out  = (const float*)d_in[10];
    float* out = (float*)d_out;

    float *proj_ptr;
    __half *xa_ptr, *ha_ptr, *wk_ptr, *wo_ptr;
    cudaGetSymbolAddress((void**)&proj_ptr, g_proj);
    cudaGetSymbolAddress((void**)&xa_ptr, g_xa);
    cudaGetSymbolAddress((void**)&ha_ptr, g_ha);
    cudaGetSymbolAddress((void**)&wk_ptr, g_wk);
    cudaGetSymbolAddress((void**)&wo_ptr, g_wo);

    cudaFuncSetAttribute(gemm_tc_kernel<true, false>,
                         cudaFuncAttributeMaxDynamicSharedMemorySize, GEMM_SMEM);
    cudaFuncSetAttribute(gemm_tc_kernel<false, true>,
                         cudaFuncAttributeMaxDynamicSharedMemorySize, GEMM_SMEM);

    // Stage 1: wave + exp projections (fp32) + x -> fp16
    proj_small_kernel<<<TOKENS / 16, 256>>>(x, w_wave, b_wave, g_wave,
                                            w_exp, b_exp, g_exp);

    // convert weights to fp16
    cvt_f16_kernel<<<(CH * CH / 4 + 255) / 256, 256>>>(w_kern, wk_ptr,
                                                       CH * CH / 4);
    cvt_f16_kernel<<<(CH * CH / 4 + 255) / 256, 256>>>(w_out, wo_ptr,
                                                       CH * CH / 4);

    // Stage 2: kern projection GEMM (+bias) via fp16 mma
    dim3 ggrid(CH / 128, TOKENS / 128);   // (8, 32)
    gemm_tc_kernel<true, false><<<ggrid, 256, GEMM_SMEM>>>(xa_ptr, wk_ptr,
                                                           b_kern, proj_ptr);

    // Stages 3+4: fused rmsnorm + attention -> hidden (fp16)
    attn_kernel<<<TOKENS, 512>>>(xa_ptr, g_kern);

    // Stage 5: output GEMM + silu via fp16 mma
    gemm_tc_kernel<false, true><<<ggrid, 256, GEMM_SMEM>>>(ha_ptr, wo_ptr,
                                                           nullptr, out);
}